// round 8
// baseline (speedup 1.0000x reference)
#include <cuda_runtime.h>
#include <cuda_fp16.h>
#include <cstdint>

// Problem constants
#define TQ    16384
#define HD    1024
#define ID    3584
#define NE    8
#define MAXTILES 320
#define KC    64
#define NK1   (HD/KC)            // 16
#define NK2   (ID/KC)            // 56

// pass1 tile: M=128, N=64 per matrix (w1+w3), 8 warps (4 wm x 2 wn), warp 32x32
// pass2 tile: M=128, N=128, 8 warps (4 wm x 2 wn), warp 32x64

// smem layouts (bytes), fp16. KC=64 => A rows 128B+16 pad, B has 64 k-rows.
#define P1_AROWB   144                         // 64 halves (128B) + 16B pad
#define P1_A_OFF   0
#define P1_B1_OFF  (128*144)                   // 18432
#define P1_BROWB   144                         // 64 halves (128B) + 16B pad
#define P1_B3_OFF  (P1_B1_OFF + 64*144)        // 27648
#define P1_STAGE   (P1_B3_OFF + 64*144)        // 36864
#define P1_NSTAGE  3
#define P1_SMEM    (P1_NSTAGE*P1_STAGE)        // 110592

#define P2_A_OFF   0
#define P2_B_OFF   (128*144)                   // 18432
#define P2_BROWB   272                         // 128 halves (256B) + 16B pad
#define P2_STAGE   (P2_B_OFF + 64*272)         // 35840
#define P2_NSTAGE  3
#define P2_SMEM    (P2_NSTAGE*P2_STAGE)        // 107520

// ---------------- device scratch ----------------
__device__ __half g_w1h[(size_t)NE * HD * ID];
__device__ __half g_w3h[(size_t)NE * HD * ID];
__device__ __half g_w2h[(size_t)NE * ID * HD];
__device__ __half g_xh [(size_t)TQ * HD];
__device__ __half g_hidh[(size_t)TQ * 2 * ID];   // SwiGLU intermediate (fp16)
__device__ float  g_part[(size_t)TQ * 2 * HD];   // weighted per-slot outputs
__device__ int    g_tok[NE * TQ];
__device__ float  g_wt [NE * TQ];
__device__ int    g_se [TQ * 2];
__device__ int    g_sp [TQ * 2];
__device__ int    g_cnt[NE];
__device__ int    g_offs[NE + 1];
__device__ int    g_tile_e[MAXTILES];
__device__ int    g_tile_r[MAXTILES];
__device__ int    g_ntiles;

// ---------------- helpers ----------------
__device__ __forceinline__ uint32_t smem_u32(const void* p) {
    uint32_t a;
    asm("{ .reg .u64 t; cvta.to.shared.u64 t, %1; cvt.u32.u64 %0, t; }" : "=r"(a) : "l"(p));
    return a;
}
__device__ __forceinline__ float silu(float x) { return x / (1.0f + __expf(-x)); }

__device__ __forceinline__ void mma_f16(float c[4], const unsigned a[4],
                                        unsigned b0, unsigned b1) {
    asm volatile(
        "mma.sync.aligned.m16n8k16.row.col.f32.f16.f16.f32 "
        "{%0,%1,%2,%3}, {%4,%5,%6,%7}, {%8,%9}, {%0,%1,%2,%3};"
        : "+f"(c[0]), "+f"(c[1]), "+f"(c[2]), "+f"(c[3])
        : "r"(a[0]), "r"(a[1]), "r"(a[2]), "r"(a[3]), "r"(b0), "r"(b1));
}

#define LDSM4(r0, r1, r2, r3, addr)                                              \
    asm volatile("ldmatrix.sync.aligned.m8n8.x4.shared.b16 {%0,%1,%2,%3}, [%4];" \
        : "=r"(r0), "=r"(r1), "=r"(r2), "=r"(r3) : "r"(addr))
#define LDSM4T(r0, r1, r2, r3, addr)                                                   \
    asm volatile("ldmatrix.sync.aligned.m8n8.x4.trans.shared.b16 {%0,%1,%2,%3}, [%4];" \
        : "=r"(r0), "=r"(r1), "=r"(r2), "=r"(r3) : "r"(addr))

#define CP_ASYNC16(dst, src) \
    asm volatile("cp.async.cg.shared.global [%0], [%1], 16;" :: "r"(dst), "l"(src))
#define CP_COMMIT()  asm volatile("cp.async.commit_group;" ::: "memory")
#define CP_WAIT(n)   asm volatile("cp.async.wait_group %0;" :: "n"(n) : "memory")

// ---------------- small kernels ----------------
__global__ void k_zero() { if (threadIdx.x < NE) g_cnt[threadIdx.x] = 0; }

// fp32 -> fp16 pre-round, all 4 tensors in one launch (grid.y selects tensor)
__global__ void k_f2h_all(const float4* __restrict__ w1, const float4* __restrict__ w3,
                          const float4* __restrict__ w2, const float4* __restrict__ x,
                          __half2* __restrict__ d1, __half2* __restrict__ d3,
                          __half2* __restrict__ d2, __half2* __restrict__ dx,
                          int nW4, int nX4) {
    const float4* src; __half2* dst; int n4;
    switch (blockIdx.y) {
        case 0: src = w1; dst = d1; n4 = nW4; break;
        case 1: src = w3; dst = d3; n4 = nW4; break;
        case 2: src = w2; dst = d2; n4 = nW4; break;
        default: src = x; dst = dx; n4 = nX4; break;
    }
    int i = blockIdx.x * blockDim.x + threadIdx.x;
    int stride = gridDim.x * blockDim.x;
    for (; i < n4; i += stride) {
        float4 v = src[i];
        dst[2 * i + 0] = __floats2half2_rn(v.x, v.y);
        dst[2 * i + 1] = __floats2half2_rn(v.z, v.w);
    }
}

__global__ void k_router(const float* __restrict__ x, const float* __restrict__ gw) {
    int gwarp = (blockIdx.x * blockDim.x + threadIdx.x) >> 5;
    int lane  = threadIdx.x & 31;
    if (gwarp >= TQ) return;
    const float* xr = x + (size_t)gwarp * HD;
    float acc[NE];
#pragma unroll
    for (int e = 0; e < NE; e++) acc[e] = 0.0f;
#pragma unroll 4
    for (int j = 0; j < HD / 32; j++) {
        int h = lane + j * 32;
        float xv = xr[h];
#pragma unroll
        for (int e = 0; e < NE; e++) acc[e] += xv * gw[e * HD + h];
    }
#pragma unroll
    for (int e = 0; e < NE; e++)
#pragma unroll
        for (int o = 16; o > 0; o >>= 1)
            acc[e] += __shfl_xor_sync(0xFFFFFFFFu, acc[e], o);
    if (lane == 0) {
        int i0 = 0;
#pragma unroll
        for (int e = 1; e < NE; e++) if (acc[e] > acc[i0]) i0 = e;
        int i1 = (i0 == 0) ? 1 : 0;
#pragma unroll
        for (int e = 0; e < NE; e++) if (e != i0 && acc[e] > acc[i1]) i1 = e;
        float w0 = 1.0f / (1.0f + expf(acc[i1] - acc[i0]));
        float w1 = 1.0f - w0;
        int p0 = atomicAdd(&g_cnt[i0], 1);
        g_tok[i0 * TQ + p0] = gwarp;  g_wt[i0 * TQ + p0] = w0;
        int p1 = atomicAdd(&g_cnt[i1], 1);
        g_tok[i1 * TQ + p1] = gwarp;  g_wt[i1 * TQ + p1] = w1;
        g_se[gwarp * 2 + 0] = i0;  g_sp[gwarp * 2 + 0] = p0;
        g_se[gwarp * 2 + 1] = i1;  g_sp[gwarp * 2 + 1] = p1;
    }
}

__global__ void k_finalize() {
    if (threadIdx.x != 0 || blockIdx.x != 0) return;
    int o = 0; g_offs[0] = 0;
    for (int e = 0; e < NE; e++) { o += g_cnt[e]; g_offs[e + 1] = o; }
    int nt = 0;
    for (int e = 0; e < NE; e++)
        for (int r = 0; r < g_cnt[e] && nt < MAXTILES; r += 128) {
            g_tile_e[nt] = e; g_tile_r[nt] = r; nt++;
        }
    g_ntiles = nt;
}

// =====================================================================
// pass1: hid = silu(Xg @ W1) * (Xg @ W3), fp16 mma m16n8k16, KC=64
// =====================================================================
__global__ void __launch_bounds__(256, 2)
k_pass1() {
    const int mt = blockIdx.y;
    if (mt >= g_ntiles) return;
    const int e   = g_tile_e[mt];
    const int r0  = g_tile_r[mt];
    const int cnt = g_cnt[e];
    const int n0  = blockIdx.x * 64;

    extern __shared__ char smem[];
    const uint32_t sbase = smem_u32(smem);

    const int tid = threadIdx.x, lane = tid & 31, warp = tid >> 5;
    const int wm = warp >> 1, wn = warp & 1;
    const int gid = lane >> 2, tig = lane & 3;

    // A gather: 2 threads per row, 64B (32 halves) each
    const int arow = tid >> 1, ahalf = tid & 1;
    int tokr = 0;
    if (r0 + arow < cnt) tokr = g_tok[e * TQ + r0 + arow];
    const char* asrc = (const char*)(g_xh + (size_t)tokr * HD) + ahalf * 64;
    const __half* w1p = g_w1h + (size_t)e * HD * ID;
    const __half* w3p = g_w3h + (size_t)e * HD * ID;

    // B copy coords: 64 rows x 8 chunks(16B) = 512 per matrix; 2 iters/thread
    auto issue_stage = [&](int kc, int s) {
        const int k0 = kc * KC;
        const uint32_t sb = sbase + (uint32_t)s * P1_STAGE;
        uint32_t adst = sb + arow * P1_AROWB + ahalf * 64;
        const char* src = asrc + (size_t)k0 * 2;
#pragma unroll
        for (int q = 0; q < 4; q++) CP_ASYNC16(adst + q * 16, src + q * 16);
#pragma unroll
        for (int it = 0; it < 2; it++) {
            int idx = tid + it * 256;
            int row = idx >> 3, c = idx & 7;
            const char* s1 = (const char*)(w1p + (size_t)(k0 + row) * ID + n0) + c * 16;
            const char* s3 = (const char*)(w3p + (size_t)(k0 + row) * ID + n0) + c * 16;
            CP_ASYNC16(sb + P1_B1_OFF + row * P1_BROWB + c * 16, s1);
            CP_ASYNC16(sb + P1_B3_OFF + row * P1_BROWB + c * 16, s3);
        }
        CP_COMMIT();
    };

    float acc1[2][4][4], acc3[2][4][4];
#pragma unroll
    for (int mi = 0; mi < 2; mi++)
#pragma unroll
        for (int ni = 0; ni < 4; ni++)
#pragma unroll
            for (int q = 0; q < 4; q++) { acc1[mi][ni][q] = 0.f; acc3[mi][ni][q] = 0.f; }

    // ldmatrix lane maps
    const int alrow = wm * 32 + (lane & 15);
    const uint32_t aoff = (uint32_t)(alrow * P1_AROWB + (lane >> 4) * 16);
    const int blrow = (lane & 7) + 8 * ((lane >> 3) & 1);
    const uint32_t boff = (uint32_t)(blrow * P1_BROWB + (wn * 32 + 8 * (lane >> 4)) * 2);

    issue_stage(0, 0);
    issue_stage(1, 1);

    for (int kc = 0; kc < NK1; kc++) {
        if (kc + 1 < NK1) { CP_WAIT(1); } else { CP_WAIT(0); }
        __syncthreads();     // single barrier per chunk: stage kc visible AND
                             // all warps finished reading stage kc-1 (3-stage safe)
        if (kc + 2 < NK1) issue_stage(kc + 2, (kc + 2) % P1_NSTAGE);

        const uint32_t sb = sbase + (uint32_t)(kc % P1_NSTAGE) * P1_STAGE;
        const uint32_t abase = sb + aoff;
        const uint32_t b1base = sb + P1_B1_OFF + boff;
        const uint32_t b3base = sb + P1_B3_OFF + boff;

#pragma unroll
        for (int ks = 0; ks < 4; ks++) {
            const int kk = ks * 16;
            unsigned a[2][4];
#pragma unroll
            for (int mi = 0; mi < 2; mi++)
                LDSM4(a[mi][0], a[mi][1], a[mi][2], a[mi][3],
                      abase + mi * (16 * P1_AROWB) + kk * 2);
#pragma unroll
            for (int p = 0; p < 2; p++) {
                unsigned r0_, r1_, r2_, r3_;
                LDSM4T(r0_, r1_, r2_, r3_, b1base + kk * P1_BROWB + p * 32);
#pragma unroll
                for (int mi = 0; mi < 2; mi++) {
                    mma_f16(acc1[mi][2 * p + 0], a[mi], r0_, r1_);
                    mma_f16(acc1[mi][2 * p + 1], a[mi], r2_, r3_);
                }
                LDSM4T(r0_, r1_, r2_, r3_, b3base + kk * P1_BROWB + p * 32);
#pragma unroll
                for (int mi = 0; mi < 2; mi++) {
                    mma_f16(acc3[mi][2 * p + 0], a[mi], r0_, r1_);
                    mma_f16(acc3[mi][2 * p + 1], a[mi], r2_, r3_);
                }
            }
        }
    }

    // epilogue: SwiGLU -> g_hidh (fp16)
    const int gofs = g_offs[e];
#pragma unroll
    for (int mi = 0; mi < 2; mi++) {
#pragma unroll
        for (int ni = 0; ni < 4; ni++) {
            int col = n0 + wn * 32 + ni * 8 + tig * 2;
            int rl0 = r0 + wm * 32 + mi * 16 + gid;
            if (rl0 < cnt) {
                __half2 h = __floats2half2_rn(
                    silu(acc1[mi][ni][0]) * acc3[mi][ni][0],
                    silu(acc1[mi][ni][1]) * acc3[mi][ni][1]);
                *(__half2*)&g_hidh[(size_t)(gofs + rl0) * ID + col] = h;
            }
            int rl1 = rl0 + 8;
            if (rl1 < cnt) {
                __half2 h = __floats2half2_rn(
                    silu(acc1[mi][ni][2]) * acc3[mi][ni][2],
                    silu(acc1[mi][ni][3]) * acc3[mi][ni][3]);
                *(__half2*)&g_hidh[(size_t)(gofs + rl1) * ID + col] = h;
            }
        }
    }
}

// =====================================================================
// pass2: g_part[slot] = wt * (hid @ W2), fp16 mma, tile M=128 N=128, KC=64
// =====================================================================
__global__ void __launch_bounds__(256, 2)
k_pass2() {
    const int mt = blockIdx.y;
    if (mt >= g_ntiles) return;
    const int e   = g_tile_e[mt];
    const int r0  = g_tile_r[mt];
    const int cnt = g_cnt[e];
    const int n0  = blockIdx.x * 128;
    const int gofs = g_offs[e];

    extern __shared__ char smem[];
    const uint32_t sbase = smem_u32(smem);

    const int tid = threadIdx.x, lane = tid & 31, warp = tid >> 5;
    const int wm = warp >> 1, wn = warp & 1;
    const int gid = lane >> 2, tig = lane & 3;

    const int arow = tid >> 1, ahalf = tid & 1;
    const int srow = (r0 + arow < cnt) ? (gofs + r0 + arow) : 0;
    const char* asrc = (const char*)(g_hidh + (size_t)srow * ID) + ahalf * 64;
    const __half* w2p = g_w2h + (size_t)e * ID * HD;

    auto issue_stage = [&](int kc, int s) {
        const int k0 = kc * KC;
        const uint32_t sb = sbase + (uint32_t)s * P2_STAGE;
        uint32_t adst = sb + arow * P1_AROWB + ahalf * 64;
        const char* src = asrc + (size_t)k0 * 2;
#pragma unroll
        for (int q = 0; q < 4; q++) CP_ASYNC16(adst + q * 16, src + q * 16);
        // B: 64 rows x 16 chunks = 1024 / 256 thr = 4 iters
#pragma unroll
        for (int it = 0; it < 4; it++) {
            int idx = tid + it * 256;
            int row = idx >> 4, c = idx & 15;
            const char* s2 = (const char*)(w2p + (size_t)(k0 + row) * HD + n0) + c * 16;
            CP_ASYNC16(sb + P2_B_OFF + row * P2_BROWB + c * 16, s2);
        }
        CP_COMMIT();
    };

    float acc[2][8][4];
#pragma unroll
    for (int mi = 0; mi < 2; mi++)
#pragma unroll
        for (int ni = 0; ni < 8; ni++)
#pragma unroll
            for (int q = 0; q < 4; q++) acc[mi][ni][q] = 0.f;

    const int alrow = wm * 32 + (lane & 15);
    const uint32_t aoff = (uint32_t)(alrow * P1_AROWB + (lane >> 4) * 16);
    const int blrow = (lane & 7) + 8 * ((lane >> 3) & 1);
    const uint32_t boff = (uint32_t)(blrow * P2_BROWB + (wn * 64 + 8 * (lane >> 4)) * 2);

    issue_stage(0, 0);
    issue_stage(1, 1);

    for (int kc = 0; kc < NK2; kc++) {
        if (kc + 1 < NK2) { CP_WAIT(1); } else { CP_WAIT(0); }
        __syncthreads();     // single barrier per chunk (3-stage safe)
        if (kc + 2 < NK2) issue_stage(kc + 2, (kc + 2) % P2_NSTAGE);

        const uint32_t sb = sbase + (uint32_t)(kc % P2_NSTAGE) * P2_STAGE;
        const uint32_t abase = sb + aoff;
        const uint32_t bbase = sb + P2_B_OFF + boff;

#pragma unroll
        for (int ks = 0; ks < 4; ks++) {
            const int kk = ks * 16;
            unsigned a[2][4];
#pragma unroll
            for (int mi = 0; mi < 2; mi++)
                LDSM4(a[mi][0], a[mi][1], a[mi][2], a[mi][3],
                      abase + mi * (16 * P1_AROWB) + kk * 2);
#pragma unroll
            for (int p = 0; p < 4; p++) {
                unsigned r0_, r1_, r2_, r3_;
                LDSM4T(r0_, r1_, r2_, r3_, bbase + kk * P2_BROWB + p * 32);
#pragma unroll
                for (int mi = 0; mi < 2; mi++) {
                    mma_f16(acc[mi][2 * p + 0], a[mi], r0_, r1_);
                    mma_f16(acc[mi][2 * p + 1], a[mi], r2_, r3_);
                }
            }
        }
    }

    // epilogue: weighted store to g_part (fp32, no atomics)
#pragma unroll
    for (int mi = 0; mi < 2; mi++) {
#pragma unroll
        for (int half = 0; half < 2; half++) {
            int rl = r0 + wm * 32 + mi * 16 + gid + half * 8;
            if (rl >= cnt) continue;
            float wgt = g_wt[e * TQ + rl];
            float* op = g_part + (size_t)(gofs + rl) * HD;
#pragma unroll
            for (int ni = 0; ni < 8; ni++) {
                int col = n0 + wn * 64 + ni * 8 + tig * 2;
                float2 v;
                v.x = acc[mi][ni][half * 2 + 0] * wgt;
                v.y = acc[mi][ni][half * 2 + 1] * wgt;
                *(float2*)(op + col) = v;
            }
        }
    }
}

// combine: out[t] = part[slot0(t)] + part[slot1(t)]
__global__ void k_combine(float* __restrict__ out) {
    const int t = blockIdx.x;
    const int j = threadIdx.x;                 // 256 threads x float4 = 1024
    int e0 = g_se[t * 2 + 0], p0 = g_sp[t * 2 + 0];
    int e1 = g_se[t * 2 + 1], p1 = g_sp[t * 2 + 1];
    const float4* a = (const float4*)(g_part + (size_t)(g_offs[e0] + p0) * HD);
    const float4* b = (const float4*)(g_part + (size_t)(g_offs[e1] + p1) * HD);
    float4 va = a[j], vb = b[j];
    float4 o = make_float4(va.x + vb.x, va.y + vb.y, va.z + vb.z, va.w + vb.w);
    ((float4*)(out + (size_t)t * HD))[j] = o;
}

// ---------------- launch ----------------
extern "C" void kernel_launch(void* const* d_in, const int* in_sizes, int n_in,
                              void* d_out, int out_size) {
    const float* x  = (const float*)d_in[0];
    const float* gw = (const float*)d_in[1];
    const float* w1 = (const float*)d_in[2];
    const float* w3 = (const float*)d_in[3];
    const float* w2 = (const float*)d_in[4];
    float* out = (float*)d_out;

    cudaFuncSetAttribute(k_pass1, cudaFuncAttributeMaxDynamicSharedMemorySize, P1_SMEM);
    cudaFuncSetAttribute(k_pass2, cudaFuncAttributeMaxDynamicSharedMemorySize, P2_SMEM);

    k_zero<<<1, 32>>>();
    k_router<<<TQ / 8, 256>>>(x, gw);
    k_finalize<<<1, 1>>>();

    // pre-round fp32 -> fp16 (all 4 tensors, one launch)
    const int W4 = NE * HD * ID / 4;           // 7,340,032
    const int X4 = TQ * HD / 4;                // 4,194,304
    __half2* w1h; cudaGetSymbolAddress((void**)&w1h, g_w1h);
    __half2* w3h; cudaGetSymbolAddress((void**)&w3h, g_w3h);
    __half2* w2h; cudaGetSymbolAddress((void**)&w2h, g_w2h);
    __half2* xh;  cudaGetSymbolAddress((void**)&xh,  g_xh);
    k_f2h_all<<<dim3(2048, 4), 256>>>((const float4*)w1, (const float4*)w3,
                                      (const float4*)w2, (const float4*)x,
                                      w1h, w3h, w2h, xh, W4, X4);

    k_pass1<<<dim3(ID / 64, MAXTILES), 256, P1_SMEM>>>();
    k_pass2<<<dim3(HD / 128, MAXTILES), 256, P2_SMEM>>>();
    k_combine<<<TQ, 256>>>(out);
}

// round 9
// speedup vs baseline: 1.0843x; 1.0843x over previous
#include <cuda_runtime.h>
#include <cuda_fp16.h>
#include <cstdint>

// Problem constants
#define TQ    16384
#define HD    1024
#define ID    3584
#define NE    8
#define MAXTILES 320
#define KC    32
#define NK1   (HD/KC)            // 32
#define NK2   (ID/KC)            // 112

// pass1 tile: M=128, N=64 per matrix (w1+w3), 8 warps (4 wm x 2 wn), warp 32x32
// pass2 tile: M=128, N=128, 8 warps (4 wm x 2 wn), warp 32x64

// smem layouts (bytes), fp16, KC=32 (R7-proven), 4 stages.
#define P1_AROWB   80                          // 32 halves (64B) + 16B pad
#define P1_A_OFF   0
#define P1_B1_OFF  (128*80)                    // 10240
#define P1_BROWB   144                         // 64 halves (128B) + 16B pad
#define P1_B3_OFF  (P1_B1_OFF + 32*144)        // 14848
#define P1_STAGE   (P1_B3_OFF + 32*144)        // 19456
#define P1_NSTAGE  4
#define P1_SMEM    (P1_NSTAGE*P1_STAGE)        // 77824

#define P2_A_OFF   0
#define P2_B_OFF   (128*80)                    // 10240
#define P2_BROWB   272                         // 128 halves (256B) + 16B pad
#define P2_STAGE   (P2_B_OFF + 32*272)         // 18944
#define P2_NSTAGE  4
#define P2_SMEM    (P2_NSTAGE*P2_STAGE)        // 75776

// ---------------- device scratch ----------------
__device__ __half g_w1h[(size_t)NE * HD * ID];
__device__ __half g_w3h[(size_t)NE * HD * ID];
__device__ __half g_w2h[(size_t)NE * ID * HD];
__device__ __half g_xh [(size_t)TQ * HD];
__device__ __half g_hidh[(size_t)TQ * 2 * ID];   // SwiGLU intermediate (fp16)
__device__ float  g_part[(size_t)TQ * 2 * HD];   // weighted per-slot outputs
__device__ int    g_tok[NE * TQ];
__device__ float  g_wt [NE * TQ];
__device__ int    g_se [TQ * 2];
__device__ int    g_sp [TQ * 2];
__device__ int    g_cnt[NE];
__device__ int    g_offs[NE + 1];
__device__ int    g_tile_e[MAXTILES];
__device__ int    g_tile_r[MAXTILES];
__device__ int    g_ntiles;

// ---------------- helpers ----------------
__device__ __forceinline__ uint32_t smem_u32(const void* p) {
    uint32_t a;
    asm("{ .reg .u64 t; cvta.to.shared.u64 t, %1; cvt.u32.u64 %0, t; }" : "=r"(a) : "l"(p));
    return a;
}
__device__ __forceinline__ float silu(float x) { return x / (1.0f + __expf(-x)); }

__device__ __forceinline__ void mma_f16(float c[4], const unsigned a[4],
                                        unsigned b0, unsigned b1) {
    asm volatile(
        "mma.sync.aligned.m16n8k16.row.col.f32.f16.f16.f32 "
        "{%0,%1,%2,%3}, {%4,%5,%6,%7}, {%8,%9}, {%0,%1,%2,%3};"
        : "+f"(c[0]), "+f"(c[1]), "+f"(c[2]), "+f"(c[3])
        : "r"(a[0]), "r"(a[1]), "r"(a[2]), "r"(a[3]), "r"(b0), "r"(b1));
}

#define LDSM4(r0, r1, r2, r3, addr)                                              \
    asm volatile("ldmatrix.sync.aligned.m8n8.x4.shared.b16 {%0,%1,%2,%3}, [%4];" \
        : "=r"(r0), "=r"(r1), "=r"(r2), "=r"(r3) : "r"(addr))
#define LDSM4T(r0, r1, r2, r3, addr)                                                   \
    asm volatile("ldmatrix.sync.aligned.m8n8.x4.trans.shared.b16 {%0,%1,%2,%3}, [%4];" \
        : "=r"(r0), "=r"(r1), "=r"(r2), "=r"(r3) : "r"(addr))

#define CP_ASYNC16(dst, src) \
    asm volatile("cp.async.cg.shared.global [%0], [%1], 16;" :: "r"(dst), "l"(src))
#define CP_COMMIT()  asm volatile("cp.async.commit_group;" ::: "memory")
#define CP_WAIT(n)   asm volatile("cp.async.wait_group %0;" :: "n"(n) : "memory")

// ---------------- small kernels ----------------
__global__ void k_zero() { if (threadIdx.x < NE) g_cnt[threadIdx.x] = 0; }

// fp32 -> fp16 pre-round, all 4 tensors in one launch (grid.y selects tensor)
__global__ void k_f2h_all(const float4* __restrict__ w1, const float4* __restrict__ w3,
                          const float4* __restrict__ w2, const float4* __restrict__ x,
                          __half2* __restrict__ d1, __half2* __restrict__ d3,
                          __half2* __restrict__ d2, __half2* __restrict__ dx,
                          int nW4, int nX4) {
    const float4* src; __half2* dst; int n4;
    switch (blockIdx.y) {
        case 0: src = w1; dst = d1; n4 = nW4; break;
        case 1: src = w3; dst = d3; n4 = nW4; break;
        case 2: src = w2; dst = d2; n4 = nW4; break;
        default: src = x; dst = dx; n4 = nX4; break;
    }
    int i = blockIdx.x * blockDim.x + threadIdx.x;
    int stride = gridDim.x * blockDim.x;
    for (; i < n4; i += stride) {
        float4 v = src[i];
        dst[2 * i + 0] = __floats2half2_rn(v.x, v.y);
        dst[2 * i + 1] = __floats2half2_rn(v.z, v.w);
    }
}

__global__ void k_router(const float* __restrict__ x, const float* __restrict__ gw) {
    int gwarp = (blockIdx.x * blockDim.x + threadIdx.x) >> 5;
    int lane  = threadIdx.x & 31;
    if (gwarp >= TQ) return;
    const float* xr = x + (size_t)gwarp * HD;
    float acc[NE];
#pragma unroll
    for (int e = 0; e < NE; e++) acc[e] = 0.0f;
#pragma unroll 4
    for (int j = 0; j < HD / 32; j++) {
        int h = lane + j * 32;
        float xv = xr[h];
#pragma unroll
        for (int e = 0; e < NE; e++) acc[e] += xv * gw[e * HD + h];
    }
#pragma unroll
    for (int e = 0; e < NE; e++)
#pragma unroll
        for (int o = 16; o > 0; o >>= 1)
            acc[e] += __shfl_xor_sync(0xFFFFFFFFu, acc[e], o);
    if (lane == 0) {
        int i0 = 0;
#pragma unroll
        for (int e = 1; e < NE; e++) if (acc[e] > acc[i0]) i0 = e;
        int i1 = (i0 == 0) ? 1 : 0;
#pragma unroll
        for (int e = 0; e < NE; e++) if (e != i0 && acc[e] > acc[i1]) i1 = e;
        float w0 = 1.0f / (1.0f + expf(acc[i1] - acc[i0]));
        float w1 = 1.0f - w0;
        int p0 = atomicAdd(&g_cnt[i0], 1);
        g_tok[i0 * TQ + p0] = gwarp;  g_wt[i0 * TQ + p0] = w0;
        int p1 = atomicAdd(&g_cnt[i1], 1);
        g_tok[i1 * TQ + p1] = gwarp;  g_wt[i1 * TQ + p1] = w1;
        g_se[gwarp * 2 + 0] = i0;  g_sp[gwarp * 2 + 0] = p0;
        g_se[gwarp * 2 + 1] = i1;  g_sp[gwarp * 2 + 1] = p1;
    }
}

__global__ void k_finalize() {
    if (threadIdx.x != 0 || blockIdx.x != 0) return;
    int o = 0; g_offs[0] = 0;
    for (int e = 0; e < NE; e++) { o += g_cnt[e]; g_offs[e + 1] = o; }
    int nt = 0;
    for (int e = 0; e < NE; e++)
        for (int r = 0; r < g_cnt[e] && nt < MAXTILES; r += 128) {
            g_tile_e[nt] = e; g_tile_r[nt] = r; nt++;
        }
    g_ntiles = nt;
}

// =====================================================================
// pass1: hid = silu(Xg @ W1) * (Xg @ W3), fp16 mma m16n8k16, KC=32, 4 stages
// =====================================================================
__global__ void __launch_bounds__(256, 2)
k_pass1() {
    const int mt = blockIdx.y;
    if (mt >= g_ntiles) return;
    const int e   = g_tile_e[mt];
    const int r0  = g_tile_r[mt];
    const int cnt = g_cnt[e];
    const int n0  = blockIdx.x * 64;

    extern __shared__ char smem[];
    const uint32_t sbase = smem_u32(smem);

    const int tid = threadIdx.x, lane = tid & 31, warp = tid >> 5;
    const int wm = warp >> 1, wn = warp & 1;
    const int gid = lane >> 2, tig = lane & 3;

    // A gather: 2 threads per row (32 halves = 64B)
    const int arow = tid >> 1, ahalf = tid & 1;
    int tokr = 0;
    if (r0 + arow < cnt) tokr = g_tok[e * TQ + r0 + arow];
    const char* asrc = (const char*)(g_xh + (size_t)tokr * HD) + ahalf * 32;
    const __half* w1p = g_w1h + (size_t)e * HD * ID;
    const __half* w3p = g_w3h + (size_t)e * HD * ID;

    // B copy coords: 32 rows x 8 chunks(16B) = 256 per matrix = 1 per thread
    const int brow = tid >> 3, bc = tid & 7;

    auto issue_stage = [&](int kc, int s) {
        const int k0 = kc * KC;
        const uint32_t sb = sbase + (uint32_t)s * P1_STAGE;
        uint32_t adst = sb + arow * P1_AROWB + ahalf * 32;
        const char* src = asrc + (size_t)k0 * 2;
        CP_ASYNC16(adst, src);
        CP_ASYNC16(adst + 16, src + 16);
        const char* s1 = (const char*)(w1p + (size_t)(k0 + brow) * ID + n0) + bc * 16;
        const char* s3 = (const char*)(w3p + (size_t)(k0 + brow) * ID + n0) + bc * 16;
        CP_ASYNC16(sb + P1_B1_OFF + brow * P1_BROWB + bc * 16, s1);
        CP_ASYNC16(sb + P1_B3_OFF + brow * P1_BROWB + bc * 16, s3);
        CP_COMMIT();
    };

    float acc1[2][4][4], acc3[2][4][4];
#pragma unroll
    for (int mi = 0; mi < 2; mi++)
#pragma unroll
        for (int ni = 0; ni < 4; ni++)
#pragma unroll
            for (int q = 0; q < 4; q++) { acc1[mi][ni][q] = 0.f; acc3[mi][ni][q] = 0.f; }

    // ldmatrix lane maps
    const int alrow = wm * 32 + (lane & 15);            // A rows
    const uint32_t aoff = (uint32_t)(alrow * P1_AROWB + (lane >> 4) * 16);
    const int blrow = (lane & 7) + 8 * ((lane >> 3) & 1);
    const uint32_t boff = (uint32_t)(blrow * P1_BROWB + (wn * 32 + 8 * (lane >> 4)) * 2);

    issue_stage(0, 0);
    issue_stage(1, 1);
    issue_stage(2, 2);

    for (int kc = 0; kc < NK1; kc++) {
        CP_WAIT(2);          // uniform accounting: one group per iter (see tail commit)
        __syncthreads();     // single barrier: stage kc visible AND all warps done
                             // reading the stage about to be overwritten (dist 4)
        if (kc + 3 < NK1) issue_stage(kc + 3, (kc + 3) & 3);
        else              CP_COMMIT();   // empty group keeps CP_WAIT(2) exact at tail

        const uint32_t sb = sbase + (uint32_t)(kc & 3) * P1_STAGE;
        const uint32_t abase = sb + aoff;
        const uint32_t b1base = sb + P1_B1_OFF + boff;
        const uint32_t b3base = sb + P1_B3_OFF + boff;

#pragma unroll
        for (int ks = 0; ks < 2; ks++) {
            const int kk = ks * 16;
            unsigned a[2][4];
#pragma unroll
            for (int mi = 0; mi < 2; mi++)
                LDSM4(a[mi][0], a[mi][1], a[mi][2], a[mi][3],
                      abase + mi * (16 * P1_AROWB) + kk * 2);
#pragma unroll
            for (int p = 0; p < 2; p++) {
                unsigned r0_, r1_, r2_, r3_;
                LDSM4T(r0_, r1_, r2_, r3_, b1base + kk * P1_BROWB + p * 32);
#pragma unroll
                for (int mi = 0; mi < 2; mi++) {
                    mma_f16(acc1[mi][2 * p + 0], a[mi], r0_, r1_);
                    mma_f16(acc1[mi][2 * p + 1], a[mi], r2_, r3_);
                }
                LDSM4T(r0_, r1_, r2_, r3_, b3base + kk * P1_BROWB + p * 32);
#pragma unroll
                for (int mi = 0; mi < 2; mi++) {
                    mma_f16(acc3[mi][2 * p + 0], a[mi], r0_, r1_);
                    mma_f16(acc3[mi][2 * p + 1], a[mi], r2_, r3_);
                }
            }
        }
    }

    // epilogue: SwiGLU -> g_hidh (fp16)
    const int gofs = g_offs[e];
#pragma unroll
    for (int mi = 0; mi < 2; mi++) {
#pragma unroll
        for (int ni = 0; ni < 4; ni++) {
            int col = n0 + wn * 32 + ni * 8 + tig * 2;
            int rl0 = r0 + wm * 32 + mi * 16 + gid;
            if (rl0 < cnt) {
                __half2 h = __floats2half2_rn(
                    silu(acc1[mi][ni][0]) * acc3[mi][ni][0],
                    silu(acc1[mi][ni][1]) * acc3[mi][ni][1]);
                *(__half2*)&g_hidh[(size_t)(gofs + rl0) * ID + col] = h;
            }
            int rl1 = rl0 + 8;
            if (rl1 < cnt) {
                __half2 h = __floats2half2_rn(
                    silu(acc1[mi][ni][2]) * acc3[mi][ni][2],
                    silu(acc1[mi][ni][3]) * acc3[mi][ni][3]);
                *(__half2*)&g_hidh[(size_t)(gofs + rl1) * ID + col] = h;
            }
        }
    }
}

// =====================================================================
// pass2: g_part[slot] = wt * (hid @ W2), fp16 mma, tile M=128 N=128, KC=32
// =====================================================================
__global__ void __launch_bounds__(256, 2)
k_pass2() {
    const int mt = blockIdx.y;
    if (mt >= g_ntiles) return;
    const int e   = g_tile_e[mt];
    const int r0  = g_tile_r[mt];
    const int cnt = g_cnt[e];
    const int n0  = blockIdx.x * 128;
    const int gofs = g_offs[e];

    extern __shared__ char smem[];
    const uint32_t sbase = smem_u32(smem);

    const int tid = threadIdx.x, lane = tid & 31, warp = tid >> 5;
    const int wm = warp >> 1, wn = warp & 1;
    const int gid = lane >> 2, tig = lane & 3;

    const int arow = tid >> 1, ahalf = tid & 1;
    const int srow = (r0 + arow < cnt) ? (gofs + r0 + arow) : 0;
    const char* asrc = (const char*)(g_hidh + (size_t)srow * ID) + ahalf * 32;
    const __half* w2p = g_w2h + (size_t)e * ID * HD;

    auto issue_stage = [&](int kc, int s) {
        const int k0 = kc * KC;
        const uint32_t sb = sbase + (uint32_t)s * P2_STAGE;
        uint32_t adst = sb + arow * P1_AROWB + ahalf * 32;
        const char* src = asrc + (size_t)k0 * 2;
        CP_ASYNC16(adst, src);
        CP_ASYNC16(adst + 16, src + 16);
        // B: 32 rows x 16 chunks = 512 / 256 thr = 2 iters
#pragma unroll
        for (int it = 0; it < 2; it++) {
            int idx = tid + it * 256;
            int row = idx >> 4, c = idx & 15;
            const char* s2 = (const char*)(w2p + (size_t)(k0 + row) * HD + n0) + c * 16;
            CP_ASYNC16(sb + P2_B_OFF + row * P2_BROWB + c * 16, s2);
        }
        CP_COMMIT();
    };

    float acc[2][8][4];
#pragma unroll
    for (int mi = 0; mi < 2; mi++)
#pragma unroll
        for (int ni = 0; ni < 8; ni++)
#pragma unroll
            for (int q = 0; q < 4; q++) acc[mi][ni][q] = 0.f;

    const int alrow = wm * 32 + (lane & 15);
    const uint32_t aoff = (uint32_t)(alrow * P1_AROWB + (lane >> 4) * 16);
    const int blrow = (lane & 7) + 8 * ((lane >> 3) & 1);
    const uint32_t boff = (uint32_t)(blrow * P2_BROWB + (wn * 64 + 8 * (lane >> 4)) * 2);

    issue_stage(0, 0);
    issue_stage(1, 1);
    issue_stage(2, 2);

    for (int kc = 0; kc < NK2; kc++) {
        CP_WAIT(2);
        __syncthreads();     // single barrier per chunk (4-stage safe)
        if (kc + 3 < NK2) issue_stage(kc + 3, (kc + 3) & 3);
        else              CP_COMMIT();

        const uint32_t sb = sbase + (uint32_t)(kc & 3) * P2_STAGE;
        const uint32_t abase = sb + aoff;
        const uint32_t bbase = sb + P2_B_OFF + boff;

#pragma unroll
        for (int ks = 0; ks < 2; ks++) {
            const int kk = ks * 16;
            unsigned a[2][4];
#pragma unroll
            for (int mi = 0; mi < 2; mi++)
                LDSM4(a[mi][0], a[mi][1], a[mi][2], a[mi][3],
                      abase + mi * (16 * P1_AROWB) + kk * 2);
#pragma unroll
            for (int p = 0; p < 4; p++) {
                unsigned r0_, r1_, r2_, r3_;
                LDSM4T(r0_, r1_, r2_, r3_, bbase + kk * P2_BROWB + p * 32);
#pragma unroll
                for (int mi = 0; mi < 2; mi++) {
                    mma_f16(acc[mi][2 * p + 0], a[mi], r0_, r1_);
                    mma_f16(acc[mi][2 * p + 1], a[mi], r2_, r3_);
                }
            }
        }
    }

    // epilogue: weighted store to g_part (fp32, no atomics)
#pragma unroll
    for (int mi = 0; mi < 2; mi++) {
#pragma unroll
        for (int half = 0; half < 2; half++) {
            int rl = r0 + wm * 32 + mi * 16 + gid + half * 8;
            if (rl >= cnt) continue;
            float wgt = g_wt[e * TQ + rl];
            float* op = g_part + (size_t)(gofs + rl) * HD;
#pragma unroll
            for (int ni = 0; ni < 8; ni++) {
                int col = n0 + wn * 64 + ni * 8 + tig * 2;
                float2 v;
                v.x = acc[mi][ni][half * 2 + 0] * wgt;
                v.y = acc[mi][ni][half * 2 + 1] * wgt;
                *(float2*)(op + col) = v;
            }
        }
    }
}

// combine: out[t] = part[slot0(t)] + part[slot1(t)]
__global__ void k_combine(float* __restrict__ out) {
    const int t = blockIdx.x;
    const int j = threadIdx.x;                 // 256 threads x float4 = 1024
    int e0 = g_se[t * 2 + 0], p0 = g_sp[t * 2 + 0];
    int e1 = g_se[t * 2 + 1], p1 = g_sp[t * 2 + 1];
    const float4* a = (const float4*)(g_part + (size_t)(g_offs[e0] + p0) * HD);
    const float4* b = (const float4*)(g_part + (size_t)(g_offs[e1] + p1) * HD);
    float4 va = a[j], vb = b[j];
    float4 o = make_float4(va.x + vb.x, va.y + vb.y, va.z + vb.z, va.w + vb.w);
    ((float4*)(out + (size_t)t * HD))[j] = o;
}

// ---------------- launch ----------------
extern "C" void kernel_launch(void* const* d_in, const int* in_sizes, int n_in,
                              void* d_out, int out_size) {
    const float* x  = (const float*)d_in[0];
    const float* gw = (const float*)d_in[1];
    const float* w1 = (const float*)d_in[2];
    const float* w3 = (const float*)d_in[3];
    const float* w2 = (const float*)d_in[4];
    float* out = (float*)d_out;

    cudaFuncSetAttribute(k_pass1, cudaFuncAttributeMaxDynamicSharedMemorySize, P1_SMEM);
    cudaFuncSetAttribute(k_pass2, cudaFuncAttributeMaxDynamicSharedMemorySize, P2_SMEM);

    k_zero<<<1, 32>>>();
    k_router<<<TQ / 8, 256>>>(x, gw);
    k_finalize<<<1, 1>>>();

    // pre-round fp32 -> fp16 (all 4 tensors, one launch)
    const int W4 = NE * HD * ID / 4;           // 7,340,032
    const int X4 = TQ * HD / 4;                // 4,194,304
    __half2* w1h; cudaGetSymbolAddress((void**)&w1h, g_w1h);
    __half2* w3h; cudaGetSymbolAddress((void**)&w3h, g_w3h);
    __half2* w2h; cudaGetSymbolAddress((void**)&w2h, g_w2h);
    __half2* xh;  cudaGetSymbolAddress((void**)&xh,  g_xh);
    k_f2h_all<<<dim3(2048, 4), 256>>>((const float4*)w1, (const float4*)w3,
                                      (const float4*)w2, (const float4*)x,
                                      w1h, w3h, w2h, xh, W4, X4);

    k_pass1<<<dim3(ID / 64, MAXTILES), 256, P1_SMEM>>>();
    k_pass2<<<dim3(HD / 128, MAXTILES), 256, P2_SMEM>>>();
    k_combine<<<TQ, 256>>>(out);
}